// round 2
// baseline (speedup 1.0000x reference)
#include <cuda_runtime.h>

#define Bsz  512
#define Ssz  2688
#define Fsz  32
#define Hsz  512
#define WEEK 672
#define NCTA 128

typedef unsigned long long u64;

// ---------------- persistent state (device globals; no allocation) ----------
__device__ float d_h0[2][Bsz * Hsz];   // ping-pong
__device__ float d_c0[Bsz * Hsz];
__device__ float d_h1[2][Bsz * Hsz];   // ping-pong
__device__ float d_c1[Bsz * Hsz];
__device__ float d_bsum0[4 * Hsz];     // bih0 + bhh0
__device__ float d_bsum1[4 * Hsz];     // bih1 + bhh1
__device__ unsigned d_bar;             // grid barrier ticket counter

__device__ __forceinline__ float sigm(float x) { return 1.f / (1.f + expf(-x)); }

// packed fp32x2 helpers (Blackwell FFMA2 — PTX-only, bit-exact fp32 per lane)
__device__ __forceinline__ u64 fma2(u64 a, u64 b, u64 c) {
    u64 d;
    asm("fma.rn.f32x2 %0, %1, %2, %3;" : "=l"(d) : "l"(a), "l"(b), "l"(c));
    return d;
}
__device__ __forceinline__ u64 pack2(float lo, float hi) {
    u64 d;
    asm("mov.b64 %0, {%1, %2};" : "=l"(d) : "f"(lo), "f"(hi));
    return d;
}
__device__ __forceinline__ float2 unpack2(u64 v) {
    float lo, hi;
    asm("mov.b64 {%0, %1}, %2;" : "=f"(lo), "=f"(hi) : "l"(v));
    return make_float2(lo, hi);
}

// release/acquire device-wide barrier (all 128 CTAs co-resident: 1 CTA/SM)
__device__ __forceinline__ void gsync() {
    __syncthreads();
    if (threadIdx.x == 0) {
        unsigned old, cur, one = 1u;
        asm volatile("atom.release.gpu.add.u32 %0, [%1], %2;"
                     : "=r"(old) : "l"(&d_bar), "r"(one) : "memory");
        unsigned target = (old / NCTA + 1u) * NCTA;
        do {
            asm volatile("ld.acquire.gpu.u32 %0, [%1];"
                         : "=r"(cur) : "l"(&d_bar) : "memory");
        } while (cur < target);
    }
    __syncthreads();
}

// ---------------- init: zero states, fold biases, reset barrier -------------
__global__ void init_state(const float* __restrict__ bih0, const float* __restrict__ bhh0,
                           const float* __restrict__ bih1, const float* __restrict__ bhh1) {
    int i = blockIdx.x * blockDim.x + threadIdx.x;
    if (i < Bsz * Hsz) {
        d_h0[0][i] = 0.f; d_h0[1][i] = 0.f; d_c0[i] = 0.f;
        d_h1[0][i] = 0.f; d_h1[1][i] = 0.f; d_c1[i] = 0.f;
    }
    if (i < 4 * Hsz) {
        d_bsum0[i] = bih0[i] + bhh0[i];
        d_bsum1[i] = bih1[i] + bhh1[i];
    }
    if (i == 0) d_bar = 0u;
}

// ---------------- packed GEMM inner product ---------------------------------
// sA: [k][m] rows of 68 floats (16B aligned), sW: [gate][k][j] rows of 34 floats.
// Thread computes (4 m as 2 packed pairs) x 2 j x 4 gates accumulators.
template <int KT>
__device__ __forceinline__ void fma_chunk2(const float* __restrict__ sA,
                                           const float* __restrict__ sW,
                                           int m0, int j0, u64 acc[4][2][2]) {
#pragma unroll
    for (int k = 0; k < KT; k++) {
        const double2 ad = *reinterpret_cast<const double2*>(sA + k * 68 + m0);
        const u64 a01 = __double_as_longlong(ad.x);
        const u64 a23 = __double_as_longlong(ad.y);
#pragma unroll
        for (int g = 0; g < 4; g++) {
            const float2 w = *reinterpret_cast<const float2*>(sW + (g * 33 + k) * 34 + j0);
            const u64 wx = pack2(w.x, w.x);
            const u64 wy = pack2(w.y, w.y);
            acc[g][0][0] = fma2(a01, wx, acc[g][0][0]);
            acc[g][0][1] = fma2(a23, wx, acc[g][0][1]);
            acc[g][1][0] = fma2(a01, wy, acc[g][1][0]);
            acc[g][1][1] = fma2(a23, wy, acc[g][1][1]);
        }
    }
}

// ---------------- the persistent kernel --------------------------------------
__global__ __launch_bounds__(256, 1) void run_all(
    const float* __restrict__ x,
    const float* __restrict__ Wih0, const float* __restrict__ Whh0,
    const float* __restrict__ Wih1, const float* __restrict__ Whh1,
    const float* __restrict__ Wout, const float* __restrict__ bout,
    float* __restrict__ out) {
    __shared__ __align__(16) float sA[33 * 68];
    __shared__ __align__(16) float sW[4 * 33 * 34];
    __shared__ float spred[64];

    const int tid = threadIdx.x;
    const int tx = tid & 15, ty = tid >> 4;
    const int m0 = ty * 4, j0 = tx * 2;
    const int jt = blockIdx.x & 15, bt = blockIdx.x >> 4;
    const int bn = jt * 32, bm = bt * 64;
    const float bout0 = bout[0];

    float ra[8], rw[16];   // staging registers

    auto loadA = [&](const float* __restrict__ src, int kc) {
#pragma unroll
        for (int i = 0; i < 8; i++) {
            int idx = tid + i * 256; int b = idx >> 5, kk = idx & 31;
            ra[i] = src[(bm + b) * Hsz + kc * 32 + kk];
        }
    };
    auto loadW = [&](const float* __restrict__ W, int kc) {
#pragma unroll
        for (int i = 0; i < 16; i++) {
            int idx = tid + i * 256; int r = idx >> 5, kk = idx & 31;
            int g = r >> 5, jj = r & 31;
            rw[i] = W[(g * Hsz + bn + jj) * Hsz + kc * 32 + kk];
        }
    };
    auto storeAW = [&]() {
#pragma unroll
        for (int i = 0; i < 8; i++) {
            int idx = tid + i * 256; int b = idx >> 5, kk = idx & 31;
            sA[kk * 68 + b] = ra[i];
        }
#pragma unroll
        for (int i = 0; i < 16; i++) {
            int idx = tid + i * 256; int r = idx >> 5, kk = idx & 31;
            int g = r >> 5, jj = r & 31;
            sW[(g * 33 + kk) * 34 + jj] = rw[i];
        }
    };

#pragma unroll 1
    for (int t = 0; t < Ssz; t++) {
        const bool use_orig = (((t / WEEK) & 1) == 0);
        const float* __restrict__ hsrc0 = d_h0[t & 1];
        float* __restrict__ hdst0 = d_h0[(t & 1) ^ 1];
        const float* __restrict__ hsrc1 = d_h1[t & 1];
        float* __restrict__ hdst1 = d_h1[(t & 1) ^ 1];

        // ---- out(t-1) = h1(t-1).Wout + bout : feeds feat0, and jt==0 writes gmem ----
        if (t > 0 && (!use_orig || jt == 0)) {
            int b = tid >> 2;
            int k0 = (tid & 3) * 128;
            const float* hp = &hsrc1[(bm + b) * Hsz + k0];
            const float* wp = &Wout[k0];
            float s = 0.f;
#pragma unroll 8
            for (int k = 0; k < 128; k++) s += hp[k] * wp[k];
            s += __shfl_down_sync(0xffffffffu, s, 2);
            s += __shfl_down_sync(0xffffffffu, s, 1);
            if ((tid & 3) == 0) {
                float val = s + bout0;
                spred[b] = val;
                if (jt == 0) out[(bm + b) * Ssz + (t - 1)] = val;
            }
        }
        __syncthreads();

        // ================= layer 0 =================
        u64 acc[4][2][2];
#pragma unroll
        for (int g = 0; g < 4; g++) {
            acc[g][0][0] = 0ull; acc[g][0][1] = 0ull;
            acc[g][1][0] = 0ull; acc[g][1][1] = 0ull;
        }

        // phase 1: K = 33 input features (feat0 | x[:,1:32] | flag)
        for (int idx = tid; idx < 64 * 33; idx += 256) {
            int b = idx / 33, f = idx - b * 33;
            int gb = bm + b;
            float v;
            if (f == 0)      v = use_orig ? x[(gb * Ssz + t) * Fsz] : spred[b];
            else if (f < 32) v = x[(gb * Ssz + t) * Fsz + f];
            else             v = use_orig ? 0.f : 1.f;
            sA[f * 68 + b] = v;
        }
        for (int idx = tid; idx < 128 * 33; idx += 256) {
            int r = idx / 33, f = idx - r * 33;
            int g = r >> 5, jj = r & 31;
            sW[(g * 33 + f) * 34 + jj] = Wih0[(g * Hsz + bn + jj) * 33 + f];
        }
        loadA(hsrc0, 0); loadW(Whh0, 0);   // prologue for phase 2 (regs only)
        __syncthreads();
        fma_chunk2<33>(sA, sW, m0, j0, acc);

        // phase 2: K = 512 recurrent, register-staged
#pragma unroll 1
        for (int kc = 0; kc < 16; kc++) {
            __syncthreads();
            storeAW();
            __syncthreads();
            if (kc < 15) { loadA(hsrc0, kc + 1); loadW(Whh0, kc + 1); }
            fma_chunk2<32>(sA, sW, m0, j0, acc);
        }

        // epilogue: LSTM cell 0
#pragma unroll
        for (int jj = 0; jj < 2; jj++) {
            int gj = bn + j0 + jj;
            float bi = d_bsum0[gj];
            float bf = d_bsum0[512 + gj];
            float bg = d_bsum0[1024 + gj];
            float bo = d_bsum0[1536 + gj];
#pragma unroll
            for (int p = 0; p < 2; p++) {
                float2 vi = unpack2(acc[0][jj][p]);
                float2 vf = unpack2(acc[1][jj][p]);
                float2 vg = unpack2(acc[2][jj][p]);
                float2 vo = unpack2(acc[3][jj][p]);
#pragma unroll
                for (int q = 0; q < 2; q++) {
                    int gb = bm + m0 + p * 2 + q;
                    float iv = sigm((q ? vi.y : vi.x) + bi);
                    float fv = sigm((q ? vf.y : vf.x) + bf);
                    float gv = tanhf((q ? vg.y : vg.x) + bg);
                    float ov = sigm((q ? vo.y : vo.x) + bo);
                    int ci = gb * Hsz + gj;
                    float cn = fv * d_c0[ci] + iv * gv;
                    d_c0[ci] = cn;
                    hdst0[ci] = ov * tanhf(cn);
                }
            }
        }
        gsync();

        // ================= layer 1 =================
#pragma unroll
        for (int g = 0; g < 4; g++) {
            acc[g][0][0] = 0ull; acc[g][0][1] = 0ull;
            acc[g][1][0] = 0ull; acc[g][1][1] = 0ull;
        }
        loadA(hdst0, 0); loadW(Wih1, 0);   // prologue (after gsync: hdst0 complete)
#pragma unroll 1
        for (int kc = 0; kc < 32; kc++) {
            __syncthreads();
            storeAW();
            __syncthreads();
            int kn = kc + 1;
            if (kn < 32) {
                if (kn < 16) { loadA(hdst0, kn);      loadW(Wih1, kn); }
                else         { loadA(hsrc1, kn - 16); loadW(Whh1, kn - 16); }
            }
            fma_chunk2<32>(sA, sW, m0, j0, acc);
        }

        // epilogue: LSTM cell 1
#pragma unroll
        for (int jj = 0; jj < 2; jj++) {
            int gj = bn + j0 + jj;
            float bi = d_bsum1[gj];
            float bf = d_bsum1[512 + gj];
            float bg = d_bsum1[1024 + gj];
            float bo = d_bsum1[1536 + gj];
#pragma unroll
            for (int p = 0; p < 2; p++) {
                float2 vi = unpack2(acc[0][jj][p]);
                float2 vf = unpack2(acc[1][jj][p]);
                float2 vg = unpack2(acc[2][jj][p]);
                float2 vo = unpack2(acc[3][jj][p]);
#pragma unroll
                for (int q = 0; q < 2; q++) {
                    int gb = bm + m0 + p * 2 + q;
                    float iv = sigm((q ? vi.y : vi.x) + bi);
                    float fv = sigm((q ? vf.y : vf.x) + bf);
                    float gv = tanhf((q ? vg.y : vg.x) + bg);
                    float ov = sigm((q ? vo.y : vo.x) + bo);
                    int ci = gb * Hsz + gj;
                    float cn = fv * d_c1[ci] + iv * gv;
                    d_c1[ci] = cn;
                    hdst1[ci] = ov * tanhf(cn);
                }
            }
        }
        gsync();
    }

    // ---- final output column: out[:, S-1] from h1(S-1) ----
    if (jt == 0) {
        const float* __restrict__ hp1 = d_h1[Ssz & 1];  // buffer written at t = S-1
        int b = tid >> 2;
        int k0 = (tid & 3) * 128;
        float s = 0.f;
#pragma unroll 8
        for (int k = 0; k < 128; k++) s += hp1[(bm + b) * Hsz + k0 + k] * Wout[k0 + k];
        s += __shfl_down_sync(0xffffffffu, s, 2);
        s += __shfl_down_sync(0xffffffffu, s, 1);
        if ((tid & 3) == 0) out[(bm + b) * Ssz + (Ssz - 1)] = s + bout0;
    }
}

// ---------------- launch ------------------------------------------------------
extern "C" void kernel_launch(void* const* d_in, const int* in_sizes, int n_in,
                              void* d_out, int out_size) {
    const float* x    = (const float*)d_in[0];
    const float* Wih0 = (const float*)d_in[1];
    const float* Whh0 = (const float*)d_in[2];
    const float* bih0 = (const float*)d_in[3];
    const float* bhh0 = (const float*)d_in[4];
    const float* Wih1 = (const float*)d_in[5];
    const float* Whh1 = (const float*)d_in[6];
    const float* bih1 = (const float*)d_in[7];
    const float* bhh1 = (const float*)d_in[8];
    const float* Wout = (const float*)d_in[9];
    const float* bout = (const float*)d_in[10];
    float* out = (float*)d_out;

    init_state<<<(Bsz * Hsz + 255) / 256, 256>>>(bih0, bhh0, bih1, bhh1);
    run_all<<<NCTA, 256>>>(x, Wih0, Whh0, Wih1, Whh1, Wout, bout, out);
}